// round 17
// baseline (speedup 1.0000x reference)
#include <cuda_runtime.h>
#include <cuda_bf16.h>

#define BB 64
#define TT 4096
#define HH 128
#define GG 384     /* 3H */
#define NPROD 64
#define NCONS 64
#define NWORK 20   /* mma.sync GEMM workers; 64+64+20 = 148 */
#define HPLANE 144 /* padded h plane: 4 quarters x 36 floats -> bank-disjoint */
#define APAD 136   /* padded A-row stride (bf16 elems): 272B -> conflict-free frags */

// Scratch (allocation-free rule: __device__ globals)
__device__ float g_y0[(size_t)BB * TT * HH];
__device__ float g_xg1[(size_t)BB * TT * GG];
__device__ float g_y1[(size_t)BB * TT * HH];
__device__ __nv_bfloat16 g_whi[GG * HH];   // w_ih1 bf16 high part
__device__ __nv_bfloat16 g_wlo[GG * HH];   // w_ih1 bf16 residual
__device__ int g_flagA[BB * 32];
__device__ int g_flagB[BB * 32];

typedef unsigned long long ull;

static __device__ __forceinline__ ull pk(float a, float b) {
    ull r; asm("mov.b64 %0, {%1, %2};" : "=l"(r) : "f"(a), "f"(b)); return r;
}
static __device__ __forceinline__ void upk(ull v, float& a, float& b) {
    asm("mov.b64 {%0, %1}, %2;" : "=f"(a), "=f"(b) : "l"(v));
}
static __device__ __forceinline__ void ffma2(ull& acc, ull a, ull b) {
    asm("fma.rn.f32x2 %0, %1, %2, %0;" : "+l"(acc) : "l"(a), "l"(b));
}
static __device__ __forceinline__ float tanha(float x) {
    float y; asm("tanh.approx.f32 %0, %1;" : "=f"(y) : "f"(x)); return y;
}
static __device__ __forceinline__ float sigfast(float x) {
    return fmaf(0.5f, tanha(0.5f * x), 0.5f);
}
static __device__ __forceinline__ int ldacq(const int* p) {
    int v; asm volatile("ld.acquire.gpu.global.b32 %0, [%1];" : "=r"(v) : "l"(p) : "memory");
    return v;
}
static __device__ __forceinline__ void strel(int* p, int v) {
    asm volatile("st.release.gpu.global.b32 [%0], %1;" :: "l"(p), "r"(v) : "memory");
}
static __device__ __forceinline__ void stplain(int* p, int v) {
    asm volatile("st.global.b32 [%0], %1;" :: "l"(p), "r"(v) : "memory");
}
// pack two floats to bf16x2; LOW half = first arg
static __device__ __forceinline__ unsigned bf2(float flo, float fhi) {
    unsigned r; asm("cvt.rn.bf16x2.f32 %0, %1, %2;" : "=r"(r) : "f"(fhi), "f"(flo));
    return r;
}
// mma.sync m16n8k16 row.col bf16 -> f32 accumulate (sm_80 baseline HMMA)
static __device__ __forceinline__ void mma16816(float* d, const unsigned* a,
                                                unsigned b0, unsigned b1) {
    asm volatile("mma.sync.aligned.m16n8k16.row.col.f32.bf16.bf16.f32 "
        "{%0,%1,%2,%3}, {%4,%5,%6,%7}, {%8,%9}, {%0,%1,%2,%3};"
        : "+f"(d[0]), "+f"(d[1]), "+f"(d[2]), "+f"(d[3])
        : "r"(a[0]), "r"(a[1]), "r"(a[2]), "r"(a[3]), "r"(b0), "r"(b1));
}

// ---- recurrence primitives (R15 winners) ----
static __device__ __forceinline__ void loadw32(ull* w, const float* __restrict__ row) {
    const float4* r4 = (const float4*)row;
#pragma unroll
    for (int i = 0; i < 8; i++) {
        float4 v = r4[i];
        w[2 * i]     = pk(v.x, v.y);
        w[2 * i + 1] = pk(v.z, v.w);
    }
}
static __device__ __forceinline__ void dot4q(const ull w[4][16], const float* hplane,
                                             int qoff9, float* v) {
    const ulonglong2* h2 = (const ulonglong2*)hplane + qoff9;
    ull a0 = 0, a1 = 0, a2 = 0, a3 = 0;
#pragma unroll
    for (int k = 0; k < 8; k++) {
        ulonglong2 q = h2[k];
        ffma2(a0, w[0][2 * k], q.x); ffma2(a0, w[0][2 * k + 1], q.y);
        ffma2(a1, w[1][2 * k], q.x); ffma2(a1, w[1][2 * k + 1], q.y);
        ffma2(a2, w[2][2 * k], q.x); ffma2(a2, w[2][2 * k + 1], q.y);
        ffma2(a3, w[3][2 * k], q.x); ffma2(a3, w[3][2 * k + 1], q.y);
    }
    float x0, x1;
    upk(a0, x0, x1); v[0] = x0 + x1;
    upk(a1, x0, x1); v[1] = x0 + x1;
    upk(a2, x0, x1); v[2] = x0 + x1;
    upk(a3, x0, x1); v[3] = x0 + x1;
}
static __device__ __forceinline__ float combine4(const float* v, int q0, int q1) {
    float s_lo = q0 ? v[0] : v[1];
    float k_lo = q0 ? v[1] : v[0];
    float s_hi = q0 ? v[2] : v[3];
    float k_hi = q0 ? v[3] : v[2];
    float u0 = k_lo + __shfl_xor_sync(0xffffffffu, s_lo, 8);
    float u1 = k_hi + __shfl_xor_sync(0xffffffffu, s_hi, 8);
    float s2 = q1 ? u0 : u1;
    float k2 = q1 ? u1 : u0;
    return k2 + __shfl_xor_sync(0xffffffffu, s2, 16);
}

// ---------- prep: split w_ih1 into bf16 hi/lo (once per launch) ----------
__global__ void __launch_bounds__(1024)
k_prep(const float* __restrict__ w_ih1) {
    int e = blockIdx.x * 1024 + threadIdx.x;
    if (e < GG * HH) {
        float f = w_ih1[e];
        float fh = __bfloat162float(__float2bfloat16(f));
        g_whi[e] = __float2bfloat16(fh);
        g_wlo[e] = __float2bfloat16(f - fh);
    }
}

// ===== Mega-kernel: 64 layer-0 producers | 64 layer-1 consumers | 20 HMMA workers
// Worker per chunk: xg1[128t,384g] = y0[128t,128k] x w_ih1^T via mma.sync bf16,
// 3-term split (err ~2^-16): Ahi.Bhi + Alo.Bhi + Ahi.Blo. A (y0 chunk) staged
// hi/lo bf16 in SMEM (APAD rows -> conflict-free frag LDS); B frags from
// L2-hot g_whi/g_wlo; bias fused at the fp32 store.
__global__ void __launch_bounds__(384, 1)
k_main(const float* __restrict__ data, const float* __restrict__ hidden,
       const float* __restrict__ w_ih0, const float* __restrict__ w_hh0,
       const float* __restrict__ b_ih0, const float* __restrict__ b_hh0,
       const float* __restrict__ w_hh1, const float* __restrict__ b_ih1,
       const float* __restrict__ b_hh1, float* __restrict__ hT) {
    __shared__ __align__(16) float hsm[2][HPLANE];
    __shared__ __align__(8) float2 s_rz[HH];
    extern __shared__ __align__(16) __nv_bfloat16 asm_[];   // Ahi[128*APAD], Alo[...]

    const int tid = threadIdx.x;
    const int warp = tid >> 5, lane = tid & 31;

    if (blockIdx.x >= NPROD + NCONS) {
        // ================== HMMA WORKER ==================
        const int wk = blockIdx.x - (NPROD + NCONS);
        __nv_bfloat16* Ahi = asm_;
        __nv_bfloat16* Alo = asm_ + 128 * APAD;

        const int gbase = warp * 32;
        const int r0 = lane >> 2;             // frag row within tile
        const int c4 = (lane & 3) * 2;        // frag col pair base

        // bias for this lane's stored columns (4 n-tiles x 2 cols)
        float bias[4][2];
#pragma unroll
        for (int nt = 0; nt < 4; nt++) {
            bias[nt][0] = b_ih1[gbase + nt * 8 + c4];
            bias[nt][1] = b_ih1[gbase + nt * 8 + c4 + 1];
        }

        for (int task = wk; task < BB * 32; task += NWORK) {
            const int c = task >> 6, b = task & 63;   // chunk-major = production order
            if (tid == 0) {
                const int* f = g_flagA + b * 32 + c;
                while (ldacq(f) == 0) __nanosleep(64);
            }
            __syncthreads();
            // Stage A = y0 chunk, split hi/lo bf16, padded rows
            const float* y0 = g_y0 + ((size_t)b * TT + (size_t)c * 128) * HH;
            for (int e = tid; e < 128 * HH; e += 384) {
                int t = e >> 7, k = e & 127;
                float f = y0[e];
                float fh = __bfloat162float(__float2bfloat16(f));
                Ahi[t * APAD + k] = __float2bfloat16(fh);
                Alo[t * APAD + k] = __float2bfloat16(f - fh);
            }
            if (tid == 0) stplain(g_flagA + b * 32 + c, 0);   // replay reset
            __syncthreads();

            float* xg = g_xg1 + ((size_t)b * TT + (size_t)c * 128) * GG;

#pragma unroll
            for (int np = 0; np < 2; np++) {
                // Hoisted B fragments for n-tiles 2np, 2np+1 (global bf16, L2-hot)
                unsigned bh[2][8][2], bl[2][8][2];
#pragma unroll
                for (int nt = 0; nt < 2; nt++) {
                    const int gr = gbase + (2 * np + nt) * 8 + r0;
                    const __nv_bfloat16* wh = g_whi + gr * HH + c4;
                    const __nv_bfloat16* wl = g_wlo + gr * HH + c4;
#pragma unroll
                    for (int ks = 0; ks < 8; ks++) {
                        bh[nt][ks][0] = *(const unsigned*)(wh + ks * 16);
                        bh[nt][ks][1] = *(const unsigned*)(wh + ks * 16 + 8);
                        bl[nt][ks][0] = *(const unsigned*)(wl + ks * 16);
                        bl[nt][ks][1] = *(const unsigned*)(wl + ks * 16 + 8);
                    }
                }
                for (int mt = 0; mt < 8; mt++) {
                    float d[2][4] = {{0.f, 0.f, 0.f, 0.f}, {0.f, 0.f, 0.f, 0.f}};
                    const __nv_bfloat16* ah = Ahi + (mt * 16 + r0) * APAD + c4;
                    const __nv_bfloat16* al = Alo + (mt * 16 + r0) * APAD + c4;
#pragma unroll
                    for (int ks = 0; ks < 8; ks++) {
                        unsigned afh[4], afl[4];
                        afh[0] = *(const unsigned*)(ah + ks * 16);
                        afh[1] = *(const unsigned*)(ah + ks * 16 + 8 * APAD);
                        afh[2] = *(const unsigned*)(ah + ks * 16 + 8);
                        afh[3] = *(const unsigned*)(ah + ks * 16 + 8 * APAD + 8);
                        afl[0] = *(const unsigned*)(al + ks * 16);
                        afl[1] = *(const unsigned*)(al + ks * 16 + 8 * APAD);
                        afl[2] = *(const unsigned*)(al + ks * 16 + 8);
                        afl[3] = *(const unsigned*)(al + ks * 16 + 8 * APAD + 8);
#pragma unroll
                        for (int nt = 0; nt < 2; nt++) {
                            mma16816(d[nt], afh, bh[nt][ks][0], bh[nt][ks][1]);
                            mma16816(d[nt], afl, bh[nt][ks][0], bh[nt][ks][1]);
                            mma16816(d[nt], afh, bl[nt][ks][0], bl[nt][ks][1]);
                        }
                    }
#pragma unroll
                    for (int nt = 0; nt < 2; nt++) {
                        const int ntile = 2 * np + nt;
                        const int gabs = gbase + ntile * 8 + c4;
                        float* o0 = xg + (size_t)(mt * 16 + r0) * GG + gabs;
                        float* o1 = o0 + 8 * GG;
                        *(float2*)o0 = make_float2(d[nt][0] + bias[ntile][0],
                                                   d[nt][1] + bias[ntile][1]);
                        *(float2*)o1 = make_float2(d[nt][2] + bias[ntile][0],
                                                   d[nt][3] + bias[ntile][1]);
                    }
                }
            }
            __syncthreads();
            if (tid == 0) strel(g_flagB + b * 32 + c, 1);
        }
        return;
    }

    // ---- recurrence thread layout (R15) ----
    const int role = warp >> 2;            // 0=r, 1=z, 2=n
    const int blk  = warp & 3;
    const int q    = lane >> 3;
    const int q0   = q & 1, q1 = q >> 1;
    const int j    = lane & 7;
    const int base = (role << 7) | (blk << 5) | (j << 2);
    const int unit = (blk << 5) | (j << 2) | (q1 << 1) | q0;
    const int grow = (role << 7) | unit;
    const int qoff9 = q * 9;
    const int hidx = blk * 36 + ((j << 2) | (q1 << 1) | q0);

    if (blockIdx.x < NPROD) {
        // ======== PRODUCER: layer-0 recurrence, batch b ========
        const int b = blockIdx.x;
        ull w[4][16];
#pragma unroll
        for (int r = 0; r < 4; r++)
            loadw32(w[r], w_hh0 + (size_t)(base + r) * HH + q * 32);
        const float wi = w_ih0[grow], bi = b_ih0[grow], bh = b_hh0[grow];

        float h = hidden[b * HH + unit];
        if (role == 2) hsm[0][hidx] = h;
        __syncthreads();

        const float* xg = data + b * TT;
        float* yp = g_y0 + (size_t)b * TT * HH + unit;
        int* fl = g_flagA + b * 32;

        int cur = 0;
        float x = xg[0];
        for (int t = 0; t < TT; t++) {
            float xn = (t + 1 < TT) ? xg[t + 1] : 0.f;
            float v[4];
            dot4q(w, hsm[cur], qoff9, v);
            float acc = combine4(v, q0, q1) + bh;
            float xi = fmaf(x, wi, bi);
            if (role == 0)      s_rz[unit].x = sigfast(acc + xi);
            else if (role == 1) s_rz[unit].y = sigfast(acc + xi);
            asm volatile("bar.sync %0, 96;" :: "r"(blk + 1) : "memory");
            if (role == 2) {
                float2 rz = s_rz[unit];
                float n = tanha(fmaf(rz.x, acc, xi));
                h = fmaf(rz.y, h - n, n);
                hsm[cur ^ 1][hidx] = h;
                yp[0] = h;
            }
            __syncthreads();
            if (((t & 127) == 127) && tid == 0) strel(fl + (t >> 7), 1);
            x = xn;
            yp += HH;
            cur ^= 1;
        }
        if (role == 2) hT[b * HH + unit] = h;
    } else {
        // ======== CONSUMER: layer-1 recurrence, batch b ========
        const int b = blockIdx.x - NPROD;
        ull w[4][16];
#pragma unroll
        for (int r = 0; r < 4; r++)
            loadw32(w[r], w_hh1 + (size_t)(base + r) * HH + q * 32);
        const float bh = b_hh1[grow];

        float h = hidden[(BB + b) * HH + unit];
        if (role == 2) hsm[0][hidx] = h;

        const float* xg = g_xg1 + (size_t)b * TT * GG + grow;
        float* yp = g_y1 + (size_t)b * TT * HH + unit;
        int* fl = g_flagB + b * 32;

        int cur = 0;
        for (int c = 0; c < 32; c++) {
            if (tid == 0) {
                while (ldacq(fl + c) == 0) __nanosleep(64);
            }
            __syncthreads();   // flag visible; also orders initial hsm write
            int xo = c * 128 * GG;
            float x = xg[xo];
            for (int tt = 0; tt < 128; tt++) {
                float xn = (tt < 127) ? xg[xo + GG] : 0.f;   // prefetch first
                float v[4];
                dot4q(w, hsm[cur], qoff9, v);
                float acc = combine4(v, q0, q1) + bh;
                if (role == 0)      s_rz[unit].x = sigfast(acc + x);
                else if (role == 1) s_rz[unit].y = sigfast(acc + x);
                asm volatile("bar.sync %0, 96;" :: "r"(blk + 1) : "memory");
                if (role == 2) {
                    float2 rz = s_rz[unit];
                    float n = tanha(fmaf(rz.x, acc, x));
                    h = fmaf(rz.y, h - n, n);
                    hsm[cur ^ 1][hidx] = h;
                    yp[0] = h;
                }
                __syncthreads();
                x = xn;
                xo += GG;
                yp += HH;
                cur ^= 1;
            }
            if (tid == 0) stplain(fl + c, 0);
        }
        if (role == 2) hT[(BB + b) * HH + unit] = h;
    }
}

// ---------- Tail: out[b,t] = relu(y1[b,t,:]) . fc_w + fc_b ----------
__global__ void __launch_bounds__(256)
k_fc(const float* __restrict__ fc_w, const float* __restrict__ fc_b,
     float* __restrict__ out) {
    const int row = blockIdx.x * 8 + (threadIdx.x >> 5);
    const int lane = threadIdx.x & 31;
    float4 yv = ((const float4*)(g_y1 + (size_t)row * HH))[lane];
    float4 wv = ((const float4*)fc_w)[lane];
    float p = fmaxf(yv.x, 0.f) * wv.x + fmaxf(yv.y, 0.f) * wv.y
            + fmaxf(yv.z, 0.f) * wv.z + fmaxf(yv.w, 0.f) * wv.w;
    p += __shfl_xor_sync(0xffffffffu, p, 16);
    p += __shfl_xor_sync(0xffffffffu, p, 8);
    p += __shfl_xor_sync(0xffffffffu, p, 4);
    p += __shfl_xor_sync(0xffffffffu, p, 2);
    p += __shfl_xor_sync(0xffffffffu, p, 1);
    if (lane == 0) out[row] = p + fc_b[0];
}

extern "C" void kernel_launch(void* const* d_in, const int* in_sizes, int n_in,
                              void* d_out, int out_size) {
    const float* data   = (const float*)d_in[0];
    const float* hidden = (const float*)d_in[1];
    const float* w_ih0  = (const float*)d_in[2];
    const float* w_hh0  = (const float*)d_in[3];
    const float* b_ih0  = (const float*)d_in[4];
    const float* b_hh0  = (const float*)d_in[5];
    const float* w_ih1  = (const float*)d_in[6];
    const float* w_hh1  = (const float*)d_in[7];
    const float* b_ih1  = (const float*)d_in[8];
    const float* b_hh1  = (const float*)d_in[9];
    const float* fc_w   = (const float*)d_in[10];
    const float* fc_b   = (const float*)d_in[11];

    float* out = (float*)d_out;
    float* hT  = out + (size_t)BB * TT;

    const int DSMEM = 2 * 128 * APAD * 2;   // Ahi + Alo bf16, 69632 B
    cudaFuncSetAttribute(k_main, cudaFuncAttributeMaxDynamicSharedMemorySize, DSMEM);

    k_prep<<<(GG * HH + 1023) / 1024, 1024>>>(w_ih1);
    k_main<<<NPROD + NCONS + NWORK, 384, DSMEM>>>(
        data, hidden, w_ih0, w_hh0, b_ih0, b_hh0,
        w_hh1, b_ih1, b_hh1, hT);
    k_fc<<<BB * TT / 8, 256>>>(fc_w, fc_b, out);
}